// round 15
// baseline (speedup 1.0000x reference)
#include <cuda_runtime.h>
#include <math.h>

#define NMAX 50000
#define EMAX 800000
#define DIN  64
#define DH   256
#define BN_EPS 1e-5f
#define SCAN_CHUNK 1024
#define PADW 132

// ---------------- scratch (device globals; no allocation allowed) ----------
// Self-cleaning protocol: g_cnt zeroed by k_gatherx (per node) after its last
// reader (k_scan_p3); g_bnsum/g_bnsq zeroed by k_gatherx block 0 after the
// previous replay's k_norm2 read them. BSS zero-init covers the first call.
__device__ float g_agg[(size_t)NMAX * DIN];   // aggregated xs (pre-projection)
__device__ float g_xl [(size_t)NMAX * DH];
__device__ float g_z  [(size_t)NMAX * DH];
__device__ int   g_cnt[NMAX];
__device__ int   g_rowstart[NMAX + 1];
__device__ int   g_fill[NMAX];
__device__ int   g_csr_src[EMAX];
__device__ int   g_blocksum[64];
__device__ float g_dinv[NMAX];
__device__ float g_bnsum[DH];
__device__ float g_bnsq [DH];
__device__ int   g_is64;

// ---------------- helpers ---------------------------------------------------
__device__ __forceinline__ int edge_at(const void* e, long long i, int is64) {
    if (is64) return (int)((const long long*)e)[i];
    return ((const int*)e)[i];
}

__device__ __forceinline__ unsigned f2tf32(float v) {
    unsigned r;
    asm("cvt.rna.tf32.f32 %0, %1;" : "=r"(r) : "f"(v));
    return r;
}

__device__ __forceinline__ void mma_tf32(float* c, const unsigned* a, const unsigned* b) {
    asm volatile(
        "mma.sync.aligned.m16n8k8.row.col.f32.tf32.tf32.f32 "
        "{%0,%1,%2,%3}, {%4,%5,%6,%7}, {%8,%9}, {%0,%1,%2,%3};\n"
        : "+f"(c[0]), "+f"(c[1]), "+f"(c[2]), "+f"(c[3])
        : "r"(a[0]), "r"(a[1]), "r"(a[2]), "r"(a[3]), "r"(b[0]), "r"(b[1]));
}

// ---------------- detect edge width (int64 has every odd word zero) ---------
__global__ void k_detect(const int* __restrict__ e, int nwords) {
    int lane = threadIdx.x;
    int acc = 0;
    for (int j = 1 + 2 * lane; j < nwords; j += 64) acc |= e[j];
#pragma unroll
    for (int o = 16; o > 0; o >>= 1) acc |= __shfl_down_sync(~0u, acc, o);
    if (lane == 0) g_is64 = (acc == 0) ? 1 : 0;
}

// ---------------- shared lin-GEMM tile body ---------------------------------
// xl[tile] = xs @ W_lin + b_lin for one 128x128 output tile, identical math
// to the proven tf32 GEMM. tile index t: brow=(ty0 + (t>>1))*128, bcol=(t&1)*128.
__device__ __forceinline__ void lin_tile_body(
        const float* __restrict__ xs,
        const float* __restrict__ Wl, const float* __restrict__ blin,
        int M, int ty0, int t,
        unsigned (*As)[PADW], unsigned (*Bs)[PADW]) {
    const int K = DIN;
    int tid = threadIdx.x;
    int wid = tid >> 5, lane = tid & 31;
    int g = lane >> 2, tig = lane & 3;
    int warp_m = wid & 1, warp_n = wid >> 1;
    int brow = (ty0 + (t >> 1)) * 128, bcol = (t & 1) * 128;

    float acc[4][4][4];
#pragma unroll
    for (int mt = 0; mt < 4; mt++)
#pragma unroll
        for (int nt = 0; nt < 4; nt++)
#pragma unroll
            for (int r = 0; r < 4; r++) acc[mt][nt][r] = 0.f;

    for (int k0 = 0; k0 < K; k0 += 32) {
#pragma unroll
        for (int l = 0; l < 4; l++) {
            int s = tid + l * 256;
            int m = s >> 3, kq = s & 7;
            float4 v = make_float4(0.f, 0.f, 0.f, 0.f);
            if (brow + m < M)
                v = *(const float4*)(xs + (size_t)(brow + m) * K + k0 + kq * 4);
            As[kq * 4 + 0][m] = f2tf32(v.x);
            As[kq * 4 + 1][m] = f2tf32(v.y);
            As[kq * 4 + 2][m] = f2tf32(v.z);
            As[kq * 4 + 3][m] = f2tf32(v.w);
        }
#pragma unroll
        for (int l = 0; l < 4; l++) {
            int s = tid + l * 256;
            int k = s >> 5, nq = s & 31;
            float4 v = *(const float4*)(Wl + (size_t)(k0 + k) * DH + bcol + nq * 4);
            Bs[k][nq * 4 + 0] = f2tf32(v.x);
            Bs[k][nq * 4 + 1] = f2tf32(v.y);
            Bs[k][nq * 4 + 2] = f2tf32(v.z);
            Bs[k][nq * 4 + 3] = f2tf32(v.w);
        }
        __syncthreads();
#pragma unroll
        for (int kk = 0; kk < 32; kk += 8) {
            unsigned af[4][4], bf[4][2];
#pragma unroll
            for (int mt = 0; mt < 4; mt++) {
                int mb = warp_m * 64 + mt * 16 + g;
                af[mt][0] = As[kk + tig    ][mb];
                af[mt][1] = As[kk + tig    ][mb + 8];
                af[mt][2] = As[kk + tig + 4][mb];
                af[mt][3] = As[kk + tig + 4][mb + 8];
            }
#pragma unroll
            for (int nt = 0; nt < 4; nt++) {
                int nb = warp_n * 32 + nt * 8 + g;
                bf[nt][0] = Bs[kk + tig    ][nb];
                bf[nt][1] = Bs[kk + tig + 4][nb];
            }
#pragma unroll
            for (int mt = 0; mt < 4; mt++)
#pragma unroll
                for (int nt = 0; nt < 4; nt++)
                    mma_tf32(acc[mt][nt], af[mt], bf[nt]);
        }
        __syncthreads();
    }

#pragma unroll
    for (int mt = 0; mt < 4; mt++) {
        int row = brow + warp_m * 64 + mt * 16 + g;
#pragma unroll
        for (int nt = 0; nt < 4; nt++) {
            int col = bcol + warp_n * 32 + nt * 8 + 2 * tig;
            float bx = blin[col], by = blin[col + 1];
            if (row < M) {
                float2 v = make_float2(acc[mt][nt][0] + bx, acc[mt][nt][1] + by);
                *(float2*)(g_xl + (size_t)row * DH + col) = v;
            }
            if (row + 8 < M) {
                float2 v = make_float2(acc[mt][nt][2] + bx, acc[mt][nt][3] + by);
                *(float2*)(g_xl + (size_t)(row + 8) * DH + col) = v;
            }
        }
    }
}

// ---------------- combined: lin-GEMM tiles [ty0,ty1) + edge-count -----------
__global__ __launch_bounds__(256) void k_count_lin(
        const void* __restrict__ edges, int E,
        const float* __restrict__ xs,
        const float* __restrict__ Wl, const float* __restrict__ blin,
        int M, int ty0, int nlin) {
    __shared__ unsigned As[32][PADW];
    __shared__ unsigned Bs[32][PADW];

    if (blockIdx.x >= nlin) {                  // ---- count path ----
        int i = (blockIdx.x - nlin) * blockDim.x + threadIdx.x;
        if (i >= E) return;
        int is64 = g_is64;
        int d = edge_at(edges, (long long)E + i, is64);
        atomicAdd(&g_cnt[d], 1);
        return;
    }
    lin_tile_body(xs, Wl, blin, M, ty0, blockIdx.x, As, Bs);
}

// ---------------- combined: lin-GEMM tiles [ty0,ty1) + CSR fill -------------
__global__ __launch_bounds__(256) void k_fill_lin(
        const void* __restrict__ edges, int E,
        const float* __restrict__ xs,
        const float* __restrict__ Wl, const float* __restrict__ blin,
        int M, int ty0, int nlin) {
    __shared__ unsigned As[32][PADW];
    __shared__ unsigned Bs[32][PADW];

    if (blockIdx.x >= nlin) {                  // ---- fill path ----
        int i = (blockIdx.x - nlin) * blockDim.x + threadIdx.x;
        if (i >= E) return;
        int is64 = g_is64;
        int s = edge_at(edges, i, is64);
        int d = edge_at(edges, (long long)E + i, is64);
        int pos = atomicAdd(&g_fill[d], 1);
        g_csr_src[pos] = s;
        return;
    }
    lin_tile_body(xs, Wl, blin, M, ty0, blockIdx.x, As, Bs);
}

// ---------------- scan: phase 1 per-chunk sums ------------------------------
__global__ void k_scan_p1(int N) {
    __shared__ int wsum[32];
    int b = blockIdx.x, tid = threadIdx.x;
    int i = b * SCAN_CHUNK + tid;
    int v = (i < N) ? g_cnt[i] : 0;
#pragma unroll
    for (int o = 16; o > 0; o >>= 1) v += __shfl_down_sync(~0u, v, o);
    if ((tid & 31) == 0) wsum[tid >> 5] = v;
    __syncthreads();
    if (tid < 32) {
        int s = wsum[tid];
#pragma unroll
        for (int o = 16; o > 0; o >>= 1) s += __shfl_down_sync(~0u, s, o);
        if (tid == 0) g_blocksum[b] = s;
    }
}

// ---------------- scan: phase 3 (block offset computed in-kernel) -----------
__global__ void k_scan_p3(int nb, int N) {
    __shared__ int wsum[32];
    __shared__ int s_off;
    int b = blockIdx.x, tid = threadIdx.x;
    int lane = tid & 31, wid = tid >> 5;

    if (wid == 0) {
        int v0 = (lane < nb) ? g_blocksum[lane] : 0;
        int v1 = (lane + 32 < nb) ? g_blocksum[lane + 32] : 0;
        int p0 = (lane < b) ? v0 : 0;
        int p1 = (lane + 32 < b) ? v1 : 0;
        int off = p0 + p1;
        int tot = v0 + v1;
#pragma unroll
        for (int o = 16; o > 0; o >>= 1) {
            off += __shfl_down_sync(~0u, off, o);
            tot += __shfl_down_sync(~0u, tot, o);
        }
        if (lane == 0) {
            s_off = off;
            if (b == 0) g_rowstart[N] = tot;
        }
    }
    __syncthreads();

    int i = b * SCAN_CHUNK + tid;
    int v = (i < N) ? g_cnt[i] : 0;
    int x = v;
#pragma unroll
    for (int o = 1; o < 32; o <<= 1) {
        int y = __shfl_up_sync(~0u, x, o);
        if (lane >= o) x += y;
    }
    if (lane == 31) wsum[wid] = x;
    __syncthreads();
    if (wid == 0) {
        int s = wsum[lane];
#pragma unroll
        for (int o = 1; o < 32; o <<= 1) {
            int y = __shfl_up_sync(~0u, s, o);
            if (lane >= o) s += y;
        }
        wsum[lane] = s;
    }
    __syncthreads();
    int excl = s_off + x - v + (wid ? wsum[wid - 1] : 0);
    if (i < N) {
        g_rowstart[i] = excl;
        g_fill[i]     = excl;
        g_dinv[i]     = rsqrtf((float)(v + 1));
    }
}

// ---------------- xs aggregation: warp per node, float2 per lane ------------
// agg[n] = dinv[n] * ( dinv[n]*xs[n] + sum_{s in N(n)} dinv[s]*xs[s] )
// Also self-cleans g_cnt (per node) and g_bnsum/g_bnsq (block 0) for the
// next graph replay.
__global__ __launch_bounds__(256) void k_gatherx(const float* __restrict__ xs, int N) {
    if (blockIdx.x == 0 && threadIdx.x < DH) {
        g_bnsum[threadIdx.x] = 0.f;
        g_bnsq [threadIdx.x] = 0.f;
    }
    int warp = (blockIdx.x * blockDim.x + threadIdx.x) >> 5;
    int lane = threadIdx.x & 31;
    if (warp >= N) return;
    int n = warp;
    if (lane == 0) g_cnt[n] = 0;
    float di = g_dinv[n];

    float2 a = ((const float2*)(xs + (size_t)n * DIN))[lane];
    a.x *= di; a.y *= di;

    int e   = g_rowstart[n];
    int end = g_rowstart[n + 1];

    for (; e + 7 < end; e += 8) {
        int   si[8];
        float wi[8];
        float2 vi[8];
#pragma unroll
        for (int u = 0; u < 8; u++) si[u] = g_csr_src[e + u];
#pragma unroll
        for (int u = 0; u < 8; u++) wi[u] = g_dinv[si[u]];
#pragma unroll
        for (int u = 0; u < 8; u++)
            vi[u] = ((const float2*)(xs + (size_t)si[u] * DIN))[lane];
#pragma unroll
        for (int u = 0; u < 8; u++) {
            a.x = fmaf(vi[u].x, wi[u], a.x);
            a.y = fmaf(vi[u].y, wi[u], a.y);
        }
    }
    for (; e < end; e++) {
        int s = g_csr_src[e];
        float w = g_dinv[s];
        float2 v = ((const float2*)(xs + (size_t)s * DIN))[lane];
        a.x = fmaf(v.x, w, a.x);
        a.y = fmaf(v.y, w, a.y);
    }
    a.x *= di; a.y *= di;
    ((float2*)(g_agg + (size_t)n * DIN))[lane] = a;
}

// ---- z GEMM: z = tanh(agg @ W_gcn + b_gcn) ---------------------------------
__global__ __launch_bounds__(256) void k_gemm_tf32(
        const float* __restrict__ B0, const float* __restrict__ bias0, int M) {
    __shared__ unsigned As[32][PADW];
    __shared__ unsigned Bs[32][PADW];
    const int K = DIN;
    const float* A = g_agg;

    int tid = threadIdx.x;
    int wid = tid >> 5, lane = tid & 31;
    int g = lane >> 2, tig = lane & 3;
    int warp_m = wid & 1, warp_n = wid >> 1;
    int brow = blockIdx.y * 128, bcol = blockIdx.x * 128;

    float acc[4][4][4];
#pragma unroll
    for (int mt = 0; mt < 4; mt++)
#pragma unroll
        for (int nt = 0; nt < 4; nt++)
#pragma unroll
            for (int r = 0; r < 4; r++) acc[mt][nt][r] = 0.f;

    for (int k0 = 0; k0 < K; k0 += 32) {
#pragma unroll
        for (int l = 0; l < 4; l++) {
            int s = tid + l * 256;
            int m = s >> 3, kq = s & 7;
            float4 v = make_float4(0.f, 0.f, 0.f, 0.f);
            if (brow + m < M)
                v = *(const float4*)(A + (size_t)(brow + m) * K + k0 + kq * 4);
            As[kq * 4 + 0][m] = f2tf32(v.x);
            As[kq * 4 + 1][m] = f2tf32(v.y);
            As[kq * 4 + 2][m] = f2tf32(v.z);
            As[kq * 4 + 3][m] = f2tf32(v.w);
        }
#pragma unroll
        for (int l = 0; l < 4; l++) {
            int s = tid + l * 256;
            int k = s >> 5, nq = s & 31;
            float4 v = *(const float4*)(B0 + (size_t)(k0 + k) * DH + bcol + nq * 4);
            Bs[k][nq * 4 + 0] = f2tf32(v.x);
            Bs[k][nq * 4 + 1] = f2tf32(v.y);
            Bs[k][nq * 4 + 2] = f2tf32(v.z);
            Bs[k][nq * 4 + 3] = f2tf32(v.w);
        }
        __syncthreads();
#pragma unroll
        for (int kk = 0; kk < 32; kk += 8) {
            unsigned af[4][4], bf[4][2];
#pragma unroll
            for (int mt = 0; mt < 4; mt++) {
                int mb = warp_m * 64 + mt * 16 + g;
                af[mt][0] = As[kk + tig    ][mb];
                af[mt][1] = As[kk + tig    ][mb + 8];
                af[mt][2] = As[kk + tig + 4][mb];
                af[mt][3] = As[kk + tig + 4][mb + 8];
            }
#pragma unroll
            for (int nt = 0; nt < 4; nt++) {
                int nb = warp_n * 32 + nt * 8 + g;
                bf[nt][0] = Bs[kk + tig    ][nb];
                bf[nt][1] = Bs[kk + tig + 4][nb];
            }
#pragma unroll
            for (int mt = 0; mt < 4; mt++)
#pragma unroll
                for (int nt = 0; nt < 4; nt++)
                    mma_tf32(acc[mt][nt], af[mt], bf[nt]);
        }
        __syncthreads();
    }

#pragma unroll
    for (int mt = 0; mt < 4; mt++) {
        int row = brow + warp_m * 64 + mt * 16 + g;
#pragma unroll
        for (int nt = 0; nt < 4; nt++) {
            int col = bcol + warp_n * 32 + nt * 8 + 2 * tig;
            float bx = bias0[col], by = bias0[col + 1];
            if (row < M) {
                float vx = tanhf(acc[mt][nt][0] + bx);
                float vy = tanhf(acc[mt][nt][1] + by);
                *(float2*)(g_z + (size_t)row * DH + col) = make_float2(vx, vy);
            }
            if (row + 8 < M) {
                float vx = tanhf(acc[mt][nt][2] + bx);
                float vy = tanhf(acc[mt][nt][3] + by);
                *(float2*)(g_z + (size_t)(row + 8) * DH + col) = make_float2(vx, vy);
            }
        }
    }
}

// ---- gate GEMM (z @ W_gate) + fused sigmoid/residual/ReLU + BN -------------
__global__ __launch_bounds__(256) void k_gate_tf32(
        const float* __restrict__ B, const float* __restrict__ bgate,
        float* __restrict__ OUT, int M) {
    __shared__ unsigned As[32][PADW];
    __shared__ unsigned Bs[32][PADW];
    __shared__ float s_sum[128], s_sq[128];
    const int K = DH;
    const float* A = g_z;

    int tid = threadIdx.x;
    int wid = tid >> 5, lane = tid & 31;
    int g = lane >> 2, tig = lane & 3;
    int warp_m = wid & 1, warp_n = wid >> 1;
    int brow = blockIdx.y * 128, bcol = blockIdx.x * 128;

    if (tid < 128) { s_sum[tid] = 0.f; s_sq[tid] = 0.f; }

    float acc[4][4][4];
#pragma unroll
    for (int mt = 0; mt < 4; mt++)
#pragma unroll
        for (int nt = 0; nt < 4; nt++)
#pragma unroll
            for (int r = 0; r < 4; r++) acc[mt][nt][r] = 0.f;

    for (int k0 = 0; k0 < K; k0 += 32) {
#pragma unroll
        for (int l = 0; l < 4; l++) {
            int s = tid + l * 256;
            int m = s >> 3, kq = s & 7;
            float4 v = make_float4(0.f, 0.f, 0.f, 0.f);
            if (brow + m < M)
                v = *(const float4*)(A + (size_t)(brow + m) * K + k0 + kq * 4);
            As[kq * 4 + 0][m] = f2tf32(v.x);
            As[kq * 4 + 1][m] = f2tf32(v.y);
            As[kq * 4 + 2][m] = f2tf32(v.z);
            As[kq * 4 + 3][m] = f2tf32(v.w);
        }
#pragma unroll
        for (int l = 0; l < 4; l++) {
            int s = tid + l * 256;
            int k = s >> 5, nq = s & 31;
            float4 v = *(const float4*)(B + (size_t)(k0 + k) * DH + bcol + nq * 4);
            Bs[k][nq * 4 + 0] = f2tf32(v.x);
            Bs[k][nq * 4 + 1] = f2tf32(v.y);
            Bs[k][nq * 4 + 2] = f2tf32(v.z);
            Bs[k][nq * 4 + 3] = f2tf32(v.w);
        }
        __syncthreads();
#pragma unroll
        for (int kk = 0; kk < 32; kk += 8) {
            unsigned af[4][4], bf[4][2];
#pragma unroll
            for (int mt = 0; mt < 4; mt++) {
                int mb = warp_m * 64 + mt * 16 + g;
                af[mt][0] = As[kk + tig    ][mb];
                af[mt][1] = As[kk + tig    ][mb + 8];
                af[mt][2] = As[kk + tig + 4][mb];
                af[mt][3] = As[kk + tig + 4][mb + 8];
            }
#pragma unroll
            for (int nt = 0; nt < 4; nt++) {
                int nb = warp_n * 32 + nt * 8 + g;
                bf[nt][0] = Bs[kk + tig    ][nb];
                bf[nt][1] = Bs[kk + tig + 4][nb];
            }
#pragma unroll
            for (int mt = 0; mt < 4; mt++)
#pragma unroll
                for (int nt = 0; nt < 4; nt++)
                    mma_tf32(acc[mt][nt], af[mt], bf[nt]);
        }
        __syncthreads();
    }

    // epilogue: g=sigmoid(acc+bg); out=relu(xl+g*(z-xl)); BN partial sums
    float csum[4][2], csq[4][2];
#pragma unroll
    for (int nt = 0; nt < 4; nt++) {
        csum[nt][0] = 0.f; csum[nt][1] = 0.f;
        csq [nt][0] = 0.f; csq [nt][1] = 0.f;
    }

#pragma unroll
    for (int mt = 0; mt < 4; mt++) {
#pragma unroll
        for (int half = 0; half < 2; half++) {
            int row = brow + warp_m * 64 + mt * 16 + g + half * 8;
            if (row >= M) continue;
#pragma unroll
            for (int nt = 0; nt < 4; nt++) {
                int col = bcol + warp_n * 32 + nt * 8 + 2 * tig;
                const float* zp = g_z  + (size_t)row * DH + col;
                const float* xp = g_xl + (size_t)row * DH + col;
                float*       op = OUT  + (size_t)row * DH + col;
                float2 zv = *(const float2*)zp;
                float2 xv = *(const float2*)xp;
#pragma unroll
                for (int c = 0; c < 2; c++) {
                    float gp = acc[mt][nt][half * 2 + c] + bgate[col + c];
                    float gg = 1.f / (1.f + expf(-gp));
                    float zz = c ? zv.y : zv.x;
                    float xx = c ? xv.y : xv.x;
                    float o = fmaf(gg, zz - xx, xx);
                    o = fmaxf(o, 0.f);
                    op[c] = o;
                    csum[nt][c] += o;
                    csq [nt][c] += o * o;
                }
            }
        }
    }
#pragma unroll
    for (int nt = 0; nt < 4; nt++) {
        int cl = warp_n * 32 + nt * 8 + 2 * tig;
        atomicAdd(&s_sum[cl],     csum[nt][0]);
        atomicAdd(&s_sum[cl + 1], csum[nt][1]);
        atomicAdd(&s_sq [cl],     csq [nt][0]);
        atomicAdd(&s_sq [cl + 1], csq [nt][1]);
    }
    __syncthreads();
    if (tid < 128) {
        atomicAdd(&g_bnsum[bcol + tid], s_sum[tid]);
        atomicAdd(&g_bnsq [bcol + tid], s_sq [tid]);
    }
}

// ---------------- norm (BN stats folded in: per-block recompute) ------------
__global__ __launch_bounds__(256) void k_norm2(float* __restrict__ OUT,
        const float* __restrict__ gamma, const float* __restrict__ beta, int N) {
    __shared__ float s_sc[DH], s_sh[DH];
    int tid = threadIdx.x;
    {
        float invn = 1.0f / (float)N;
        float mu  = g_bnsum[tid] * invn;
        float var = g_bnsq[tid] * invn - mu * mu;
        float sc  = gamma[tid] * rsqrtf(var + BN_EPS);
        s_sc[tid] = sc;
        s_sh[tid] = beta[tid] - mu * sc;
    }
    __syncthreads();
    int i = blockIdx.x * blockDim.x + tid;
    int total = N * (DH / 4);
    if (i >= total) return;
    int c4 = i & 63;
    float4 sc = ((const float4*)s_sc)[c4];
    float4 sh = ((const float4*)s_sh)[c4];
    float4 v = ((float4*)OUT)[i];
    v.x = fmaf(v.x, sc.x, sh.x);
    v.y = fmaf(v.y, sc.y, sh.y);
    v.z = fmaf(v.z, sc.z, sh.z);
    v.w = fmaf(v.w, sc.w, sh.w);
    ((float4*)OUT)[i] = v;
}

// ---------------- launch ----------------------------------------------------
extern "C" void kernel_launch(void* const* d_in, const int* in_sizes, int n_in,
                              void* d_out, int out_size) {
    const float* xs     = (const float*)d_in[0];
    const void*  edges  =               d_in[1];
    const float* W_gcn  = (const float*)d_in[2];
    const float* b_gcn  = (const float*)d_in[3];
    const float* W_lin  = (const float*)d_in[4];
    const float* b_lin  = (const float*)d_in[5];
    const float* W_gate = (const float*)d_in[6];
    const float* b_gate = (const float*)d_in[7];
    const float* gamma  = (const float*)d_in[8];
    const float* beta   = (const float*)d_in[9];
    float* out = (float*)d_out;

    int N = in_sizes[0] / DIN;     // 50000
    int E = in_sizes[1] / 2;       // 800000

    int nwords = 2048;
    if (2 * E < nwords) nwords = 2 * E;

    int nb = (N + SCAN_CHUNK - 1) / SCAN_CHUNK;
    if (nb > 64) nb = 64;          // g_blocksum capacity (N<=65536 here)

    int ntiles = (N + 127) / 128;  // 391 row tiles for the lin GEMM
    int tyh = ntiles / 2;          // first half rides with count
    int nlin1 = 2 * tyh;
    int nlin2 = 2 * (ntiles - tyh);
    int ncnt = (E + 255) / 256;

    k_detect<<<1, 32>>>((const int*)edges, nwords);
    k_count_lin<<<nlin1 + ncnt, 256>>>(edges, E, xs, W_lin, b_lin, N, 0, nlin1);
    k_scan_p1<<<nb, SCAN_CHUNK>>>(N);
    k_scan_p3<<<nb, SCAN_CHUNK>>>(nb, N);
    k_fill_lin<<<nlin2 + ncnt, 256>>>(edges, E, xs, W_lin, b_lin, N, tyh, nlin2);

    k_gatherx<<<(N + 7) / 8, 256>>>(xs, N);

    dim3 g1(2, (N + 127) / 128);
    k_gemm_tf32<<<g1, 256>>>(W_gcn, b_gcn, N);     // -> g_z
    k_gate_tf32<<<g1, 256>>>(W_gate, b_gate, out, N);

    k_norm2<<<(N * (DH / 4) + 255) / 256, 256>>>(out, gamma, beta, N);
}